// round 13
// baseline (speedup 1.0000x reference)
#include <cuda_runtime.h>
#include <cuda_bf16.h>
#include <cstdint>

#define NUM_CLASSES 100000
#define EMBED 512
#define BATCH_N 4096
#define LAMBDA_C 0.01f
#define ALPHA_C 0.1f

#define NCS ((size_t)NUM_CLASSES * EMBED)   // 51,200,000 floats
#define N4  (NCS / 4)                        // 12,800,000 float4s
#define COPY_GRID ((unsigned)(N4 / 256))     // 50,000 blocks
#define BUILD_BLOCKS 16
#define FIX_BLOCKS 512                       // 512*8 warps = 4096 samples

// Zero-initialized at load; commit kernel restores zeros each call, so the
// invariant holds across graph replays. g_head[c]: 0=untouched, i+1=head.
__device__ int g_head[NUM_CLASSES];
__device__ int g_next[BATCH_N];
__device__ unsigned g_done;
__device__ float g_loss;
__device__ float4 g_upd[BATCH_N * (EMBED / 4)];   // 8 MB scratch (per-sample rows)

// Kernel 1: streaming copy + embedded build + overlapped fixup-compute.
__global__ __launch_bounds__(256)
void copy_build_fix_kernel(const float4* __restrict__ src,
                           float* __restrict__ dst,
                           const int* __restrict__ y,
                           const float4* __restrict__ batch4) {
    const int bid = blockIdx.x;
    const int tid = threadIdx.x;

    // ---- build (blocks 0-15, first-scheduled) ----
    if (bid < BUILD_BLOCKS) {
        if (bid == 0 && tid == 0) g_loss = 0.0f;   // before gate opens
        const int i = bid * 256 + tid;
        const int c = y[i];
        const int old = atomicExch(&g_head[c], i + 1);
        g_next[i] = old;
        __threadfence();                           // release chains + g_loss
        __syncthreads();
        if (tid == 0) atomicAdd(&g_done, 1u);
    }

    // ---- unconditional copy (every block; R2-proven hot path) ----
    const size_t q = (size_t)bid * 256 + tid;
    float4 v = __ldcs(src + q);
    float* d = dst + q * 4;                        // dst = out+1, misaligned
    __stcs(d + 0, v.x);
    __stcs(d + 1, v.y);
    __stcs(d + 2, v.z);
    __stcs(d + 3, v.w);

    // ---- fixup compute into scratch (blocks 16..527, overlapped) ----
    if (bid >= BUILD_BLOCKS && bid < BUILD_BLOCKS + FIX_BLOCKS) {
        if (tid == 0) {
            while (*(volatile unsigned*)&g_done < (unsigned)BUILD_BLOCKS)
                __nanosleep(64);
            __threadfence();                       // acquire chain writes
        }
        __syncthreads();

        const int i    = (bid - BUILD_BLOCKS) * 8 + (tid >> 5);  // sample
        const int lane = tid & 31;
        const int c    = __ldg(y + i);
        const size_t crow = (size_t)c * (EMBED / 4);
        const size_t brow = (size_t)i * (EMBED / 4);
        const bool is_head = (__ldcg(&g_head[c]) == i + 1);

        float ls = 0.f;
        #pragma unroll
        for (int k = 0; k < 4; k++) {
            const int off = k * 32 + lane;
            float4 c4 = src[crow + off];           // L2-resident (just copied)
            float4 b4 = batch4[brow + off];
            float dx = b4.x - c4.x, dy = b4.y - c4.y;
            float dz = b4.z - c4.z, dw = b4.w - c4.w;
            ls += dx*dx + dy*dy + dz*dz + dw*dw;
            if (is_head) {
                float ax = dx, ay = dy, az = dz, aw = dw;
                int s = __ldcg(&g_next[i]);
                while (s > 0) {                    // dup chain (rare, short)
                    float4 q4 = batch4[(size_t)(s - 1) * (EMBED / 4) + off];
                    ax += q4.x - c4.x; ay += q4.y - c4.y;
                    az += q4.z - c4.z; aw += q4.w - c4.w;
                    s = __ldcg(&g_next[s - 1]);
                }
                g_upd[brow + off] = make_float4(c4.x + ALPHA_C * ax,
                                                c4.y + ALPHA_C * ay,
                                                c4.z + ALPHA_C * az,
                                                c4.w + ALPHA_C * aw);
            }
        }
        #pragma unroll
        for (int o = 16; o > 0; o >>= 1)
            ls += __shfl_xor_sync(0xFFFFFFFFu, ls, o);
        if (lane == 0) atomicAdd(&g_loss, ls);
    }
}

// Kernel 2: commit touched rows from scratch + publish loss + reset globals.
__global__ __launch_bounds__(256)
void commit_kernel(const int* __restrict__ y,
                   float* __restrict__ dst,
                   float* __restrict__ loss_out) {
    const int i    = (blockIdx.x * 256 + threadIdx.x) >> 5;   // sample
    const int lane = threadIdx.x & 31;
    const int c    = __ldg(y + i);

    if (blockIdx.x == 0 && threadIdx.x == 0) {
        loss_out[0] = g_loss * (LAMBDA_C / (float)BATCH_N);
        g_loss = 0.0f;
        g_done = 0u;
    }

    if (__ldcg(&g_head[c]) == i + 1) {             // head: sole writer of row c
        const size_t brow = (size_t)i * (EMBED / 4);
        float* drow = dst + (size_t)c * EMBED;     // misaligned: scalar stores
        #pragma unroll
        for (int k = 0; k < 4; k++) {
            const int off = k * 32 + lane;
            float4 u = g_upd[brow + off];
            float* p = drow + off * 4;
            p[0] = u.x; p[1] = u.y; p[2] = u.z; p[3] = u.w;
        }
        if (lane == 0) g_head[c] = 0;              // restore zero-invariant
    }
}

extern "C" void kernel_launch(void* const* d_in, const int* in_sizes, int n_in,
                              void* d_out, int out_size) {
    const int*   y       = (const int*)d_in[0];
    const float* batch   = (const float*)d_in[1];
    const float* centers = (const float*)d_in[2];

    float* out = (float*)d_out;

    float* loss_ptr;
    float* new_centers;
    if (out_size == (int)(NCS + 1)) {
        loss_ptr = out;
        new_centers = out + 1;
    } else {
        new_centers = out;
        loss_ptr = out + NCS;
    }

    copy_build_fix_kernel<<<COPY_GRID, 256>>>(
        reinterpret_cast<const float4*>(centers), new_centers, y,
        reinterpret_cast<const float4*>(batch));

    commit_kernel<<<BATCH_N / 8, 256>>>(y, new_centers, loss_ptr);
}

// round 14
// speedup vs baseline: 1.0135x; 1.0135x over previous
#include <cuda_runtime.h>
#include <cuda_bf16.h>
#include <cstdint>

#define NUM_CLASSES 100000
#define EMBED 512
#define BATCH_N 4096
#define LAMBDA_C 0.01f
#define ALPHA_C 0.1f

#define NCS ((size_t)NUM_CLASSES * EMBED)   // 51,200,000 floats
#define N4  (NCS / 4)                        // 12,800,000 float4s
#define COPY_GRID ((unsigned)(N4 / 256))     // 50,000 blocks

// Zero-initialized at load; fixup restores zeros each call, so the invariant
// holds across graph replays. g_head[c]: 0 = untouched, i+1 = sample i head.
__device__ int g_head[NUM_CLASSES];
__device__ int g_next[BATCH_N];

// Kernel 1: pure streaming copy; blocks 0-15 also build the chains (nobody
// reads g_head here -> no gating), block 16 zeroes the loss slot.
__global__ __launch_bounds__(256)
void copy_build_kernel(const float4* __restrict__ src,
                       float* __restrict__ dst,
                       const int* __restrict__ y,
                       float* __restrict__ loss) {
    const int bid = blockIdx.x;
    const int tid = threadIdx.x;

    if (bid < 16) {                              // build: 16*256 = 4096
        const int i = bid * 256 + tid;
        const int c = y[i];
        const int old = atomicExch(&g_head[c], i + 1);
        g_next[i] = old;
    } else if (bid == 16 && tid == 0) {
        *loss = 0.0f;
    }

    // unconditional copy: aligned LDG.128 + 4x scalar STG.32 (dst = out+1)
    const size_t q = (size_t)bid * 256 + tid;
    float4 v = __ldcs(src + q);
    float* d = dst + q * 4;
    __stcs(d + 0, v.x);
    __stcs(d + 1, v.y);
    __stcs(d + 2, v.z);
    __stcs(d + 3, v.w);
}

// Kernel 2: fixup, BLOCK per sample (4096 blocks x 128 thr) for max latency
// hiding. Every block adds its own loss term; the chain-head block overwrites
// the touched row (sole writer per class) and restores g_head[c] = 0.
__global__ __launch_bounds__(128)
void fixup_kernel(const int* __restrict__ y,
                  const float4* __restrict__ batch4,
                  const float4* __restrict__ centers4,
                  float* __restrict__ dst,
                  float* __restrict__ loss) {
    const int i = blockIdx.x;           // sample
    const int t = threadIdx.x;          // 0..127, one float4 each
    const int c = __ldg(y + i);

    float4 c4 = __ldg(centers4 + (size_t)c * (EMBED / 4) + t);
    float4 b4 = __ldg(batch4 + (size_t)i * (EMBED / 4) + t);

    float dx = b4.x - c4.x, dy = b4.y - c4.y;
    float dz = b4.z - c4.z, dw = b4.w - c4.w;

    // own loss term (duplicates each contribute)
    float ls = dx * dx + dy * dy + dz * dz + dw * dw;
    #pragma unroll
    for (int off = 16; off > 0; off >>= 1)
        ls += __shfl_xor_sync(0xFFFFFFFFu, ls, off);
    __shared__ float wsum[4];
    if ((t & 31) == 0) wsum[t >> 5] = ls;
    __syncthreads();
    if (t == 0) {
        float tot = wsum[0] + wsum[1] + wsum[2] + wsum[3];
        atomicAdd(loss, tot * (LAMBDA_C / (float)BATCH_N));
    }

    // chain head: sole writer of row c
    if (__ldcg(&g_head[c]) == i + 1) {
        float ax = dx, ay = dy, az = dz, aw = dw;
        int s = __ldcg(&g_next[i]);
        while (s > 0) {                 // rare duplicate chain
            float4 q4 = __ldg(batch4 + (size_t)(s - 1) * (EMBED / 4) + t);
            ax += q4.x - c4.x; ay += q4.y - c4.y;
            az += q4.z - c4.z; aw += q4.w - c4.w;
            s = __ldcg(&g_next[s - 1]);
        }
        float* d = dst + (size_t)c * EMBED + 4 * t;   // misaligned: scalars
        d[0] = c4.x + ALPHA_C * ax;
        d[1] = c4.y + ALPHA_C * ay;
        d[2] = c4.z + ALPHA_C * az;
        d[3] = c4.w + ALPHA_C * aw;

        if (t == 0) g_head[c] = 0;      // restore zero-invariant
    }
}

extern "C" void kernel_launch(void* const* d_in, const int* in_sizes, int n_in,
                              void* d_out, int out_size) {
    const int*   y       = (const int*)d_in[0];
    const float* batch   = (const float*)d_in[1];
    const float* centers = (const float*)d_in[2];

    float* out = (float*)d_out;

    float* loss_ptr;
    float* new_centers;
    if (out_size == (int)(NCS + 1)) {
        loss_ptr = out;
        new_centers = out + 1;
    } else {
        new_centers = out;
        loss_ptr = out + NCS;
    }

    // 1) copy at full rate; builds chains + zeroes loss on the side
    copy_build_kernel<<<COPY_GRID, 256>>>(
        reinterpret_cast<const float4*>(centers), new_centers, y, loss_ptr);

    // 2) block-per-sample fixup + loss; restores g_head zeros
    fixup_kernel<<<BATCH_N, 128>>>(y,
        reinterpret_cast<const float4*>(batch),
        reinterpret_cast<const float4*>(centers),
        new_centers, loss_ptr);
}